// round 4
// baseline (speedup 1.0000x reference)
#include <cuda_runtime.h>
#include <cuda_bf16.h>

static const int NN = 200000;
static const int NE = 3200000;
static const int NG = 400;

// Scratch (device globals; no runtime allocation allowed)
__device__ int   g_degi[NN];
__device__ int   g_off[NN + 1];
__device__ int   g_cursor[NN];
__device__ int   g_csr[NE];
__device__ float g_bufA[(size_t)NN * 128];
__device__ float g_bufB[(size_t)NN * 48];
__device__ float g_z[(size_t)NN * 48];
__device__ float g_agg[(size_t)NN * 48];
__device__ float g_cnt[NG];

// ---------------------------------------------------------------------------
// packed f32x2 helpers (sm_100+ PTX; SASS FFMA2/FADD2 — 2x fp32 throughput)
__device__ __forceinline__ unsigned long long f2bcast(float v) {
    unsigned long long r;
    asm("mov.b64 %0, {%1, %1};" : "=l"(r) : "f"(v));
    return r;
}
__device__ __forceinline__ void f2fma(unsigned long long& d, unsigned long long a,
                                      unsigned long long b) {
    asm("fma.rn.f32x2 %0, %1, %2, %0;" : "+l"(d) : "l"(a), "l"(b));
}
__device__ __forceinline__ void f2add(unsigned long long& d, unsigned long long a) {
    asm("add.rn.f32x2 %0, %0, %1;" : "+l"(d) : "l"(a));
}
__device__ __forceinline__ float2 f2unpack(unsigned long long v) {
    float2 r;
    asm("mov.b64 {%0, %1}, %2;" : "=f"(r.x), "=f"(r.y) : "l"(v));
    return r;
}

// ---------------------------------------------------------------------------
__global__ void k_degree(const int* __restrict__ dst) {
    int e = blockIdx.x * blockDim.x + threadIdx.x;
    if (e < NE) atomicAdd(&g_degi[dst[e]], 1);
}

// single-block exclusive scan of g_degi -> g_off
__global__ void k_scan() {
    const int T = 1024;
    const int ITEMS = (NN + T) / T;
    __shared__ int part[T];
    int t = threadIdx.x;
    int base = t * ITEMS;
    int s = 0;
#pragma unroll 4
    for (int i = 0; i < ITEMS; i++) {
        int j = base + i;
        if (j < NN) s += g_degi[j];
    }
    part[t] = s;
    __syncthreads();
    for (int d = 1; d < T; d <<= 1) {
        int v = 0;
        if (t >= d) v = part[t - d];
        __syncthreads();
        if (t >= d) part[t] += v;
        __syncthreads();
    }
    int run = (t == 0) ? 0 : part[t - 1];
    for (int i = 0; i < ITEMS; i++) {
        int j = base + i;
        if (j <= NN) g_off[j] = run;
        if (j < NN) run += g_degi[j];
    }
}

__global__ void k_build(const int* __restrict__ src, const int* __restrict__ dst) {
    int e = blockIdx.x * blockDim.x + threadIdx.x;
    if (e >= NE) return;
    int p = atomicAdd(&g_cursor[dst[e]], 1);
    g_csr[p] = src[e];
}

// ---------------------------------------------------------------------------
// multi-edge-parallel packed CSR gather + mean.
// Warp = 1 node; SLOTS edge slots x (32/SLOTS) float4-lanes; f32x2 accumulate.
template <int DIM, int SLOTS>
__global__ void k_gather4(const float* __restrict__ z, float* __restrict__ agg) {
    constexpr int F4L = 32 / SLOTS;
    constexpr int NF4 = DIM / 4;
    int gt = blockIdx.x * blockDim.x + threadIdx.x;
    int v = gt >> 5;
    if (v >= NN) return;
    int lane = gt & 31;
    int slot = lane / F4L;
    int f4 = lane % F4L;
    bool act = (f4 < NF4);

    int beg = g_off[v];
    int end = g_off[v + 1];
    unsigned long long a01 = 0ull, a23 = 0ull;

    int e = beg;
    for (; e + 2 * SLOTS <= end; e += 2 * SLOTS) {
        int s0 = g_csr[e + slot];
        int s1 = g_csr[e + SLOTS + slot];
        if (act) {
            ulonglong2 t0 = reinterpret_cast<const ulonglong2*>(z + (size_t)s0 * DIM)[f4];
            ulonglong2 t1 = reinterpret_cast<const ulonglong2*>(z + (size_t)s1 * DIM)[f4];
            f2add(a01, t0.x);
            f2add(a23, t0.y);
            f2add(a01, t1.x);
            f2add(a23, t1.y);
        }
    }
    for (; e < end; e += SLOTS) {
        int myE = e + slot;
        if (myE < end && act) {
            int s0 = g_csr[myE];
            ulonglong2 t0 = reinterpret_cast<const ulonglong2*>(z + (size_t)s0 * DIM)[f4];
            f2add(a01, t0.x);
            f2add(a23, t0.y);
        }
    }
    float2 p01 = f2unpack(a01);
    float2 p23 = f2unpack(a23);
#pragma unroll
    for (int m = F4L; m < 32; m <<= 1) {
        p01.x += __shfl_xor_sync(0xFFFFFFFFu, p01.x, m);
        p01.y += __shfl_xor_sync(0xFFFFFFFFu, p01.y, m);
        p23.x += __shfl_xor_sync(0xFFFFFFFFu, p23.x, m);
        p23.y += __shfl_xor_sync(0xFFFFFFFFu, p23.y, m);
    }
    float inv = 1.0f / fmaxf((float)(end - beg), 1.0f);
    if (slot == 0 && act) {
        float4 o = make_float4(p01.x * inv, p01.y * inv, p23.x * inv, p23.y * inv);
        reinterpret_cast<float4*>(agg + (size_t)v * DIM)[f4] = o;
    }
}

// scalar gather for tiny DIM (=5)
template <int DIM>
__global__ void k_gatherS(const float* __restrict__ z, float* __restrict__ agg) {
    int gt = blockIdx.x * blockDim.x + threadIdx.x;
    int v = gt >> 5;
    int lane = gt & 31;
    if (v >= NN) return;
    int beg = g_off[v];
    int end = g_off[v + 1];
    float acc = 0.0f;
    int e = beg;
    for (; e + 2 <= end; e += 2) {
        int s0 = g_csr[e];
        int s1 = g_csr[e + 1];
        if (lane < DIM)
            acc += z[(size_t)s0 * DIM + lane] + z[(size_t)s1 * DIM + lane];
    }
    if (e < end && lane < DIM) acc += z[(size_t)g_csr[e] * DIM + lane];
    float inv = 1.0f / fmaxf((float)(end - beg), 1.0f);
    if (lane < DIM) agg[(size_t)v * DIM + lane] = acc * inv;
}

// ---------------------------------------------------------------------------
// f32x2-packed register-tiled projection: thread -> float4 of outputs x NV nodes.
// out = act( h@W + (ADD_AGG ? agg + bias : 0) )
template <int DIN, int DOUT, int NV, bool ADD_AGG, bool RELU>
__global__ void k_proj(const float* __restrict__ h, const float* __restrict__ W,
                       const float* __restrict__ agg, const float* __restrict__ bias,
                       float* __restrict__ out) {
    constexpr int OG = DOUT / 4;
    long long t = (long long)blockIdx.x * blockDim.x + threadIdx.x;
    int oq = (int)(t % OG);
    long long ng = t / OG;
    int n0 = (int)(ng * NV);
    if (n0 >= NN) return;

    unsigned long long a01[NV], a23[NV];
#pragma unroll
    for (int i = 0; i < NV; i++) {
        if (ADD_AGG) {
            int node = min(n0 + i, NN - 1);
            ulonglong2 b2 = reinterpret_cast<const ulonglong2*>(bias)[oq];
            ulonglong2 g2 = reinterpret_cast<const ulonglong2*>(agg + (size_t)node * DOUT)[oq];
            a01[i] = b2.x; a23[i] = b2.y;
            f2add(a01[i], g2.x);
            f2add(a23[i], g2.y);
        } else {
            a01[i] = 0ull; a23[i] = 0ull;
        }
    }

#pragma unroll
    for (int k = 0; k < DIN; k += 4) {
        ulonglong2 w0 = reinterpret_cast<const ulonglong2*>(W + (size_t)(k + 0) * DOUT)[oq];
        ulonglong2 w1 = reinterpret_cast<const ulonglong2*>(W + (size_t)(k + 1) * DOUT)[oq];
        ulonglong2 w2 = reinterpret_cast<const ulonglong2*>(W + (size_t)(k + 2) * DOUT)[oq];
        ulonglong2 w3 = reinterpret_cast<const ulonglong2*>(W + (size_t)(k + 3) * DOUT)[oq];
#pragma unroll
        for (int i = 0; i < NV; i++) {
            int node = min(n0 + i, NN - 1);
            float4 hv = reinterpret_cast<const float4*>(h + (size_t)node * DIN)[k >> 2];
            unsigned long long hx = f2bcast(hv.x), hy = f2bcast(hv.y);
            unsigned long long hz = f2bcast(hv.z), hw = f2bcast(hv.w);
            f2fma(a01[i], hx, w0.x); f2fma(a23[i], hx, w0.y);
            f2fma(a01[i], hy, w1.x); f2fma(a23[i], hy, w1.y);
            f2fma(a01[i], hz, w2.x); f2fma(a23[i], hz, w2.y);
            f2fma(a01[i], hw, w3.x); f2fma(a23[i], hw, w3.y);
        }
    }

#pragma unroll
    for (int i = 0; i < NV; i++) {
        if (n0 + i < NN) {
            float2 p01 = f2unpack(a01[i]);
            float2 p23 = f2unpack(a23[i]);
            float4 r = make_float4(p01.x, p01.y, p23.x, p23.y);
            if (RELU) {
                r.x = fmaxf(r.x, 0.f); r.y = fmaxf(r.y, 0.f);
                r.z = fmaxf(r.z, 0.f); r.w = fmaxf(r.w, 0.f);
            }
            reinterpret_cast<float4*>(out + (size_t)(n0 + i) * DOUT)[oq] = r;
        }
    }
}

// Fused layer-0: out = relu( feat@Ws + agg@Wn + b ), DIN=32, DOUT=128 (packed)
template <int NV>
__global__ void k_sage0(const float* __restrict__ feat, const float* __restrict__ agg,
                        const float* __restrict__ Ws, const float* __restrict__ Wn,
                        const float* __restrict__ bias, float* __restrict__ out) {
    constexpr int DIN = 32, DOUT = 128, OG = 32;
    long long t = (long long)blockIdx.x * blockDim.x + threadIdx.x;
    int oq = (int)(t % OG);
    long long ng = t / OG;
    int n0 = (int)(ng * NV);
    if (n0 >= NN) return;

    ulonglong2 b2 = reinterpret_cast<const ulonglong2*>(bias)[oq];
    unsigned long long a01[NV], a23[NV];
#pragma unroll
    for (int i = 0; i < NV; i++) { a01[i] = b2.x; a23[i] = b2.y; }

#pragma unroll
    for (int k = 0; k < DIN; k += 4) {
        ulonglong2 s0 = reinterpret_cast<const ulonglong2*>(Ws + (size_t)(k + 0) * DOUT)[oq];
        ulonglong2 s1 = reinterpret_cast<const ulonglong2*>(Ws + (size_t)(k + 1) * DOUT)[oq];
        ulonglong2 s2 = reinterpret_cast<const ulonglong2*>(Ws + (size_t)(k + 2) * DOUT)[oq];
        ulonglong2 s3 = reinterpret_cast<const ulonglong2*>(Ws + (size_t)(k + 3) * DOUT)[oq];
        ulonglong2 m0 = reinterpret_cast<const ulonglong2*>(Wn + (size_t)(k + 0) * DOUT)[oq];
        ulonglong2 m1 = reinterpret_cast<const ulonglong2*>(Wn + (size_t)(k + 1) * DOUT)[oq];
        ulonglong2 m2 = reinterpret_cast<const ulonglong2*>(Wn + (size_t)(k + 2) * DOUT)[oq];
        ulonglong2 m3 = reinterpret_cast<const ulonglong2*>(Wn + (size_t)(k + 3) * DOUT)[oq];
#pragma unroll
        for (int i = 0; i < NV; i++) {
            int node = min(n0 + i, NN - 1);
            float4 hv = reinterpret_cast<const float4*>(feat + (size_t)node * DIN)[k >> 2];
            float4 av = reinterpret_cast<const float4*>(agg + (size_t)node * DIN)[k >> 2];
            unsigned long long hx = f2bcast(hv.x), hy = f2bcast(hv.y);
            unsigned long long hz = f2bcast(hv.z), hw = f2bcast(hv.w);
            f2fma(a01[i], hx, s0.x); f2fma(a23[i], hx, s0.y);
            f2fma(a01[i], hy, s1.x); f2fma(a23[i], hy, s1.y);
            f2fma(a01[i], hz, s2.x); f2fma(a23[i], hz, s2.y);
            f2fma(a01[i], hw, s3.x); f2fma(a23[i], hw, s3.y);
            unsigned long long ax = f2bcast(av.x), ay = f2bcast(av.y);
            unsigned long long az = f2bcast(av.z), aw = f2bcast(av.w);
            f2fma(a01[i], ax, m0.x); f2fma(a23[i], ax, m0.y);
            f2fma(a01[i], ay, m1.x); f2fma(a23[i], ay, m1.y);
            f2fma(a01[i], az, m2.x); f2fma(a23[i], az, m2.y);
            f2fma(a01[i], aw, m3.x); f2fma(a23[i], aw, m3.y);
        }
    }

#pragma unroll
    for (int i = 0; i < NV; i++) {
        if (n0 + i < NN) {
            float2 p01 = f2unpack(a01[i]);
            float2 p23 = f2unpack(a23[i]);
            float4 r = make_float4(fmaxf(p01.x, 0.f), fmaxf(p01.y, 0.f),
                                   fmaxf(p23.x, 0.f), fmaxf(p23.y, 0.f));
            reinterpret_cast<float4*>(out + (size_t)(n0 + i) * DOUT)[oq] = r;
        }
    }
}

// ---------------------------------------------------------------------------
// scalar fallbacks for tiny (DOUT=5) layer
template <int DIN, int DOUT>
__global__ void k_gemmS(const float* __restrict__ h, const float* __restrict__ W,
                        float* __restrict__ z) {
    long long idx = (long long)blockIdx.x * blockDim.x + threadIdx.x;
    if (idx >= (long long)NN * DOUT) return;
    int v = (int)(idx / DOUT);
    int o = (int)(idx % DOUT);
    const float* hrow = h + (size_t)v * DIN;
    float acc = 0.0f;
#pragma unroll
    for (int k = 0; k < DIN; k++) acc = fmaf(hrow[k], W[k * DOUT + o], acc);
    z[idx] = acc;
}

template <int DIN, int DOUT, bool RELU>
__global__ void k_postS(const float* __restrict__ h, const float* __restrict__ aggn,
                        const float* __restrict__ Ws, const float* __restrict__ bias,
                        float* __restrict__ out) {
    long long idx = (long long)blockIdx.x * blockDim.x + threadIdx.x;
    if (idx >= (long long)NN * DOUT) return;
    int v = (int)(idx / DOUT);
    int o = (int)(idx % DOUT);
    const float* hrow = h + (size_t)v * DIN;
    float acc = bias[o] + aggn[idx];
#pragma unroll
    for (int k = 0; k < DIN; k++) acc = fmaf(hrow[k], Ws[k * DOUT + o], acc);
    out[idx] = RELU ? fmaxf(acc, 0.0f) : acc;
}

// ---------------------------------------------------------------------------
// fused readout: per-node accumulate counts + features (sorted gid -> REDUX-aggregated)
__global__ void k_readout(const float* __restrict__ h, const int* __restrict__ gid,
                          float* __restrict__ out) {
    int v = blockIdx.x * blockDim.x + threadIdx.x;
    if (v >= NN) return;
    int g = gid[v];
    atomicAdd(&g_cnt[g], 1.0f);
#pragma unroll
    for (int f = 0; f < 5; f++) atomicAdd(&out[g * 5 + f], h[(size_t)v * 5 + f]);
}

__global__ void k_final(float* __restrict__ out) {
    int i = blockIdx.x * blockDim.x + threadIdx.x;
    if (i < NG * 5) out[i] /= fmaxf(g_cnt[i / 5], 1.0f);
}

// ---------------------------------------------------------------------------
static inline int blks(long long n, int t) { return (int)((n + t - 1) / t); }

extern "C" void kernel_launch(void* const* d_in, const int* in_sizes, int n_in,
                              void* d_out, int out_size) {
    const float* feat = (const float*)d_in[0];
    const int* src = (const int*)d_in[1];
    const int* dst = (const int*)d_in[2];
    const int* gid = (const int*)d_in[3];
    const float* Ws0 = (const float*)d_in[4];
    const float* Wn0 = (const float*)d_in[5];
    const float* b0  = (const float*)d_in[6];
    const float* Ws1 = (const float*)d_in[7];
    const float* Wn1 = (const float*)d_in[8];
    const float* b1  = (const float*)d_in[9];
    const float* Ws2 = (const float*)d_in[10];
    const float* Wn2 = (const float*)d_in[11];
    const float* b2  = (const float*)d_in[12];
    const float* Ws3 = (const float*)d_in[13];
    const float* Wn3 = (const float*)d_in[14];
    const float* b3  = (const float*)d_in[15];
    float* out = (float*)d_out;

    float *bufA, *bufB, *z, *agg, *cnt;
    int *degi, *off, *cursor;
    cudaGetSymbolAddress((void**)&bufA, g_bufA);
    cudaGetSymbolAddress((void**)&bufB, g_bufB);
    cudaGetSymbolAddress((void**)&z, g_z);
    cudaGetSymbolAddress((void**)&agg, g_agg);
    cudaGetSymbolAddress((void**)&cnt, g_cnt);
    cudaGetSymbolAddress((void**)&degi, g_degi);
    cudaGetSymbolAddress((void**)&off, g_off);
    cudaGetSymbolAddress((void**)&cursor, g_cursor);

    const int T = 256;

    // ---- CSR build ----
    cudaMemsetAsync(degi, 0, NN * sizeof(int));
    k_degree<<<blks(NE, T), T>>>(dst);
    k_scan<<<1, 1024>>>();
    cudaMemcpyAsync(cursor, off, NN * sizeof(int), cudaMemcpyDeviceToDevice);
    k_build<<<blks(NE, T), T>>>(src, dst);

    // ---- layer 0: 32 -> 128, relu ----
    k_gather4<32, 4><<<blks((long long)NN * 32, T), T>>>(feat, agg);
    {
        long long th = (long long)((NN + 3) / 4) * 32;
        k_sage0<4><<<blks(th, T), T>>>(feat, agg, Ws0, Wn0, b0, bufA);
    }

    // ---- layer 1: 128 -> 48, relu ----
    {
        long long th = (long long)((NN + 7) / 8) * 12;
        k_proj<128, 48, 8, false, false><<<blks(th, T), T>>>(bufA, Wn1, nullptr, nullptr, z);
    }
    k_gather4<48, 2><<<blks((long long)NN * 32, T), T>>>(z, agg);
    {
        long long th = (long long)((NN + 7) / 8) * 12;
        k_proj<128, 48, 8, true, true><<<blks(th, T), T>>>(bufA, Ws1, agg, b1, bufB);
    }

    // ---- layer 2: 48 -> 28, relu ----
    {
        long long th = (long long)((NN + 7) / 8) * 7;
        k_proj<48, 28, 8, false, false><<<blks(th, T), T>>>(bufB, Wn2, nullptr, nullptr, z);
    }
    k_gather4<28, 4><<<blks((long long)NN * 32, T), T>>>(z, agg);
    {
        long long th = (long long)((NN + 7) / 8) * 7;
        k_proj<48, 28, 8, true, true><<<blks(th, T), T>>>(bufB, Ws2, agg, b2, bufA);
    }

    // ---- layer 3: 28 -> 5, linear (scalar path) ----
    k_gemmS<28, 5><<<blks((long long)NN * 5, T), T>>>(bufA, Wn3, z);
    k_gatherS<5><<<blks((long long)NN * 32, T), T>>>(z, agg);
    k_postS<28, 5, false><<<blks((long long)NN * 5, T), T>>>(bufA, agg, Ws3, b3, bufB);

    // ---- readout ----
    cudaMemsetAsync(out, 0, NG * 5 * sizeof(float));
    cudaMemsetAsync(cnt, 0, NG * sizeof(float));
    k_readout<<<blks(NN, T), T>>>(bufB, gid, out);
    k_final<<<blks(NG * 5, T), T>>>(out);
}

// round 5
// speedup vs baseline: 1.2493x; 1.2493x over previous
#include <cuda_runtime.h>
#include <cuda_bf16.h>

static const int NN = 200000;
static const int NE = 3200000;
static const int NG = 400;
static const int NB = (NN + 1023) / 1024;  // 196 scan blocks

// Scratch (device globals; no runtime allocation allowed)
__device__ int   g_degi[NN];
__device__ int   g_off[NN + 1];
__device__ int   g_cursor[NN];
__device__ int   g_csr[NE];
__device__ int   g_bsum[256];
__device__ float g_bufA[(size_t)NN * 128];
__device__ float g_bufB[(size_t)NN * 48];
__device__ float g_z[(size_t)NN * 48];
__device__ float g_agg[(size_t)NN * 48];
__device__ float g_cnt[NG];

// ---------------------------------------------------------------------------
__global__ void k_degree(const int* __restrict__ dst) {
    int e = blockIdx.x * blockDim.x + threadIdx.x;
    if (e < NE) atomicAdd(&g_degi[dst[e]], 1);
}

// ---- parallel exclusive scan of g_degi -> g_off (3 passes, all coalesced) ----
__global__ void k_scan1() {  // NB blocks x 1024: block sums
    __shared__ int sh[1024];
    int t = threadIdx.x;
    int j = blockIdx.x * 1024 + t;
    sh[t] = (j < NN) ? g_degi[j] : 0;
    __syncthreads();
    for (int d = 512; d > 0; d >>= 1) {
        if (t < d) sh[t] += sh[t + d];
        __syncthreads();
    }
    if (t == 0) g_bsum[blockIdx.x] = sh[0];
}

__global__ void k_scan2() {  // 1 block x 256: exclusive scan of block sums
    __shared__ int sh[256];
    int t = threadIdx.x;
    int v = (t < NB) ? g_bsum[t] : 0;
    sh[t] = v;
    __syncthreads();
    for (int d = 1; d < 256; d <<= 1) {
        int x = (t >= d) ? sh[t - d] : 0;
        __syncthreads();
        sh[t] += x;
        __syncthreads();
    }
    g_bsum[t] = sh[t] - v;  // exclusive
}

__global__ void k_scan3() {  // NB blocks x 1024: in-block scan + offset; writes off + cursor
    __shared__ int sh[1024];
    int t = threadIdx.x;
    int j = blockIdx.x * 1024 + t;
    int v = (j < NN) ? g_degi[j] : 0;
    sh[t] = v;
    __syncthreads();
    for (int d = 1; d < 1024; d <<= 1) {
        int x = (t >= d) ? sh[t - d] : 0;
        __syncthreads();
        sh[t] += x;
        __syncthreads();
    }
    int excl = sh[t] - v + g_bsum[blockIdx.x];
    if (j < NN) {
        g_off[j] = excl;
        g_cursor[j] = excl;
    }
    if (j == NN - 1) g_off[NN] = excl + v;
}

__global__ void k_build(const int* __restrict__ src, const int* __restrict__ dst) {
    int e = blockIdx.x * blockDim.x + threadIdx.x;
    if (e >= NE) return;
    int p = atomicAdd(&g_cursor[dst[e]], 1);
    g_csr[p] = src[e];
}

// ---------------------------------------------------------------------------
// multi-edge-parallel float4 CSR gather + mean: agg[v] = sum z[nbr] / max(deg,1)
// Warp = 1 node; SLOTS edge slots x (32/SLOTS) float4-lanes; 4 edges/slot in flight.
template <int DIM, int SLOTS>
__global__ void k_gather4(const float* __restrict__ z, float* __restrict__ agg) {
    constexpr int F4L = 32 / SLOTS;
    constexpr int NF4 = DIM / 4;
    int gt = blockIdx.x * blockDim.x + threadIdx.x;
    int v = gt >> 5;
    if (v >= NN) return;
    int lane = gt & 31;
    int slot = lane / F4L;
    int f4 = lane % F4L;
    bool act = (f4 < NF4);

    int beg = g_off[v];
    int end = g_off[v + 1];
    float4 acc = make_float4(0.f, 0.f, 0.f, 0.f);

    int e = beg;
    for (; e + 4 * SLOTS <= end; e += 4 * SLOTS) {
        int s0 = g_csr[e + slot];
        int s1 = g_csr[e + SLOTS + slot];
        int s2 = g_csr[e + 2 * SLOTS + slot];
        int s3 = g_csr[e + 3 * SLOTS + slot];
        if (act) {
            float4 t0 = __ldg(reinterpret_cast<const float4*>(z + (size_t)s0 * DIM) + f4);
            float4 t1 = __ldg(reinterpret_cast<const float4*>(z + (size_t)s1 * DIM) + f4);
            float4 t2 = __ldg(reinterpret_cast<const float4*>(z + (size_t)s2 * DIM) + f4);
            float4 t3 = __ldg(reinterpret_cast<const float4*>(z + (size_t)s3 * DIM) + f4);
            acc.x += (t0.x + t1.x) + (t2.x + t3.x);
            acc.y += (t0.y + t1.y) + (t2.y + t3.y);
            acc.z += (t0.z + t1.z) + (t2.z + t3.z);
            acc.w += (t0.w + t1.w) + (t2.w + t3.w);
        }
    }
    for (; e < end; e += SLOTS) {
        int myE = e + slot;
        if (myE < end && act) {
            int s0 = g_csr[myE];
            float4 t0 = __ldg(reinterpret_cast<const float4*>(z + (size_t)s0 * DIM) + f4);
            acc.x += t0.x;
            acc.y += t0.y;
            acc.z += t0.z;
            acc.w += t0.w;
        }
    }
#pragma unroll
    for (int m = F4L; m < 32; m <<= 1) {
        acc.x += __shfl_xor_sync(0xFFFFFFFFu, acc.x, m);
        acc.y += __shfl_xor_sync(0xFFFFFFFFu, acc.y, m);
        acc.z += __shfl_xor_sync(0xFFFFFFFFu, acc.z, m);
        acc.w += __shfl_xor_sync(0xFFFFFFFFu, acc.w, m);
    }
    float inv = 1.0f / fmaxf((float)(end - beg), 1.0f);
    if (slot == 0 && act) {
        float4 o = make_float4(acc.x * inv, acc.y * inv, acc.z * inv, acc.w * inv);
        reinterpret_cast<float4*>(agg + (size_t)v * DIM)[f4] = o;
    }
}

// scalar gather for tiny DIM (=5)
template <int DIM>
__global__ void k_gatherS(const float* __restrict__ z, float* __restrict__ agg) {
    int gt = blockIdx.x * blockDim.x + threadIdx.x;
    int v = gt >> 5;
    int lane = gt & 31;
    if (v >= NN) return;
    int beg = g_off[v];
    int end = g_off[v + 1];
    float acc = 0.0f;
    int e = beg;
    for (; e + 2 <= end; e += 2) {
        int s0 = g_csr[e];
        int s1 = g_csr[e + 1];
        if (lane < DIM)
            acc += z[(size_t)s0 * DIM + lane] + z[(size_t)s1 * DIM + lane];
    }
    if (e < end && lane < DIM) acc += z[(size_t)g_csr[e] * DIM + lane];
    float inv = 1.0f / fmaxf((float)(end - beg), 1.0f);
    if (lane < DIM) agg[(size_t)v * DIM + lane] = acc * inv;
}

// ---------------------------------------------------------------------------
// Register-tiled projection: each thread -> float4 of outputs x NV nodes.
template <int DIN, int DOUT, int NV, bool ADD_AGG, bool RELU>
__global__ void k_proj(const float* __restrict__ h, const float* __restrict__ W,
                       const float* __restrict__ agg, const float* __restrict__ bias,
                       float* __restrict__ out) {
    constexpr int OG = DOUT / 4;
    long long t = (long long)blockIdx.x * blockDim.x + threadIdx.x;
    int oq = (int)(t % OG);
    long long ng = t / OG;
    int n0 = (int)(ng * NV);
    if (n0 >= NN) return;

    float4 acc[NV];
#pragma unroll
    for (int i = 0; i < NV; i++) {
        int node = min(n0 + i, NN - 1);
        if (ADD_AGG) {
            float4 b4 = __ldg(reinterpret_cast<const float4*>(bias) + oq);
            float4 a4 = __ldg(reinterpret_cast<const float4*>(agg + (size_t)node * DOUT) + oq);
            acc[i] = make_float4(b4.x + a4.x, b4.y + a4.y, b4.z + a4.z, b4.w + a4.w);
        } else {
            acc[i] = make_float4(0.f, 0.f, 0.f, 0.f);
        }
    }

#pragma unroll
    for (int k = 0; k < DIN; k += 4) {
        float4 w0 = __ldg(reinterpret_cast<const float4*>(W + (size_t)(k + 0) * DOUT) + oq);
        float4 w1 = __ldg(reinterpret_cast<const float4*>(W + (size_t)(k + 1) * DOUT) + oq);
        float4 w2 = __ldg(reinterpret_cast<const float4*>(W + (size_t)(k + 2) * DOUT) + oq);
        float4 w3 = __ldg(reinterpret_cast<const float4*>(W + (size_t)(k + 3) * DOUT) + oq);
#pragma unroll
        for (int i = 0; i < NV; i++) {
            int node = min(n0 + i, NN - 1);
            float4 hv = __ldg(reinterpret_cast<const float4*>(h + (size_t)node * DIN) + (k >> 2));
            acc[i].x = fmaf(hv.x, w0.x, fmaf(hv.y, w1.x, fmaf(hv.z, w2.x, fmaf(hv.w, w3.x, acc[i].x))));
            acc[i].y = fmaf(hv.x, w0.y, fmaf(hv.y, w1.y, fmaf(hv.z, w2.y, fmaf(hv.w, w3.y, acc[i].y))));
            acc[i].z = fmaf(hv.x, w0.z, fmaf(hv.y, w1.z, fmaf(hv.z, w2.z, fmaf(hv.w, w3.z, acc[i].z))));
            acc[i].w = fmaf(hv.x, w0.w, fmaf(hv.y, w1.w, fmaf(hv.z, w2.w, fmaf(hv.w, w3.w, acc[i].w))));
        }
    }

#pragma unroll
    for (int i = 0; i < NV; i++) {
        if (n0 + i < NN) {
            float4 r = acc[i];
            if (RELU) {
                r.x = fmaxf(r.x, 0.f); r.y = fmaxf(r.y, 0.f);
                r.z = fmaxf(r.z, 0.f); r.w = fmaxf(r.w, 0.f);
            }
            reinterpret_cast<float4*>(out + (size_t)(n0 + i) * DOUT)[oq] = r;
        }
    }
}

// Fused layer-0: out = relu( feat@Ws + agg@Wn + b ), DIN=32, DOUT=128
template <int NV>
__global__ void k_sage0(const float* __restrict__ feat, const float* __restrict__ agg,
                        const float* __restrict__ Ws, const float* __restrict__ Wn,
                        const float* __restrict__ bias, float* __restrict__ out) {
    constexpr int DIN = 32, DOUT = 128, OG = 32;
    long long t = (long long)blockIdx.x * blockDim.x + threadIdx.x;
    int oq = (int)(t % OG);
    long long ng = t / OG;
    int n0 = (int)(ng * NV);
    if (n0 >= NN) return;

    float4 b4 = __ldg(reinterpret_cast<const float4*>(bias) + oq);
    float4 acc[NV];
#pragma unroll
    for (int i = 0; i < NV; i++) acc[i] = b4;

#pragma unroll
    for (int k = 0; k < DIN; k += 4) {
        float4 ws0 = __ldg(reinterpret_cast<const float4*>(Ws + (size_t)(k + 0) * DOUT) + oq);
        float4 ws1 = __ldg(reinterpret_cast<const float4*>(Ws + (size_t)(k + 1) * DOUT) + oq);
        float4 ws2 = __ldg(reinterpret_cast<const float4*>(Ws + (size_t)(k + 2) * DOUT) + oq);
        float4 ws3 = __ldg(reinterpret_cast<const float4*>(Ws + (size_t)(k + 3) * DOUT) + oq);
        float4 wn0 = __ldg(reinterpret_cast<const float4*>(Wn + (size_t)(k + 0) * DOUT) + oq);
        float4 wn1 = __ldg(reinterpret_cast<const float4*>(Wn + (size_t)(k + 1) * DOUT) + oq);
        float4 wn2 = __ldg(reinterpret_cast<const float4*>(Wn + (size_t)(k + 2) * DOUT) + oq);
        float4 wn3 = __ldg(reinterpret_cast<const float4*>(Wn + (size_t)(k + 3) * DOUT) + oq);
#pragma unroll
        for (int i = 0; i < NV; i++) {
            int node = min(n0 + i, NN - 1);
            float4 hv = __ldg(reinterpret_cast<const float4*>(feat + (size_t)node * DIN) + (k >> 2));
            float4 av = __ldg(reinterpret_cast<const float4*>(agg + (size_t)node * DIN) + (k >> 2));
            acc[i].x = fmaf(hv.x, ws0.x, fmaf(hv.y, ws1.x, fmaf(hv.z, ws2.x, fmaf(hv.w, ws3.x, acc[i].x))));
            acc[i].y = fmaf(hv.x, ws0.y, fmaf(hv.y, ws1.y, fmaf(hv.z, ws2.y, fmaf(hv.w, ws3.y, acc[i].y))));
            acc[i].z = fmaf(hv.x, ws0.z, fmaf(hv.y, ws1.z, fmaf(hv.z, ws2.z, fmaf(hv.w, ws3.z, acc[i].z))));
            acc[i].w = fmaf(hv.x, ws0.w, fmaf(hv.y, ws1.w, fmaf(hv.z, ws2.w, fmaf(hv.w, ws3.w, acc[i].w))));
            acc[i].x = fmaf(av.x, wn0.x, fmaf(av.y, wn1.x, fmaf(av.z, wn2.x, fmaf(av.w, wn3.x, acc[i].x))));
            acc[i].y = fmaf(av.x, wn0.y, fmaf(av.y, wn1.y, fmaf(av.z, wn2.y, fmaf(av.w, wn3.y, acc[i].y))));
            acc[i].z = fmaf(av.x, wn0.z, fmaf(av.y, wn1.z, fmaf(av.z, wn2.z, fmaf(av.w, wn3.z, acc[i].z))));
            acc[i].w = fmaf(av.x, wn0.w, fmaf(av.y, wn1.w, fmaf(av.z, wn2.w, fmaf(av.w, wn3.w, acc[i].w))));
        }
    }

#pragma unroll
    for (int i = 0; i < NV; i++) {
        if (n0 + i < NN) {
            float4 r = acc[i];
            r.x = fmaxf(r.x, 0.f); r.y = fmaxf(r.y, 0.f);
            r.z = fmaxf(r.z, 0.f); r.w = fmaxf(r.w, 0.f);
            reinterpret_cast<float4*>(out + (size_t)(n0 + i) * DOUT)[oq] = r;
        }
    }
}

// ---------------------------------------------------------------------------
// scalar fallbacks for tiny (DOUT=5) layer
template <int DIN, int DOUT>
__global__ void k_gemmS(const float* __restrict__ h, const float* __restrict__ W,
                        float* __restrict__ z) {
    long long idx = (long long)blockIdx.x * blockDim.x + threadIdx.x;
    if (idx >= (long long)NN * DOUT) return;
    int v = (int)(idx / DOUT);
    int o = (int)(idx % DOUT);
    const float* hrow = h + (size_t)v * DIN;
    float acc = 0.0f;
#pragma unroll
    for (int k = 0; k < DIN; k++) acc = fmaf(hrow[k], W[k * DOUT + o], acc);
    z[idx] = acc;
}

template <int DIN, int DOUT, bool RELU>
__global__ void k_postS(const float* __restrict__ h, const float* __restrict__ aggn,
                        const float* __restrict__ Ws, const float* __restrict__ bias,
                        float* __restrict__ out) {
    long long idx = (long long)blockIdx.x * blockDim.x + threadIdx.x;
    if (idx >= (long long)NN * DOUT) return;
    int v = (int)(idx / DOUT);
    int o = (int)(idx % DOUT);
    const float* hrow = h + (size_t)v * DIN;
    float acc = bias[o] + aggn[idx];
#pragma unroll
    for (int k = 0; k < DIN; k++) acc = fmaf(hrow[k], Ws[k * DOUT + o], acc);
    out[idx] = RELU ? fmaxf(acc, 0.0f) : acc;
}

// ---------------------------------------------------------------------------
__global__ void k_readout(const float* __restrict__ h, const int* __restrict__ gid,
                          float* __restrict__ out) {
    int v = blockIdx.x * blockDim.x + threadIdx.x;
    if (v >= NN) return;
    int g = gid[v];
    atomicAdd(&g_cnt[g], 1.0f);
#pragma unroll
    for (int f = 0; f < 5; f++) atomicAdd(&out[g * 5 + f], h[(size_t)v * 5 + f]);
}

__global__ void k_final(float* __restrict__ out) {
    int i = blockIdx.x * blockDim.x + threadIdx.x;
    if (i < NG * 5) out[i] /= fmaxf(g_cnt[i / 5], 1.0f);
}

// ---------------------------------------------------------------------------
static inline int blks(long long n, int t) { return (int)((n + t - 1) / t); }

extern "C" void kernel_launch(void* const* d_in, const int* in_sizes, int n_in,
                              void* d_out, int out_size) {
    const float* feat = (const float*)d_in[0];
    const int* src = (const int*)d_in[1];
    const int* dst = (const int*)d_in[2];
    const int* gid = (const int*)d_in[3];
    const float* Ws0 = (const float*)d_in[4];
    const float* Wn0 = (const float*)d_in[5];
    const float* b0  = (const float*)d_in[6];
    const float* Ws1 = (const float*)d_in[7];
    const float* Wn1 = (const float*)d_in[8];
    const float* b1  = (const float*)d_in[9];
    const float* Ws2 = (const float*)d_in[10];
    const float* Wn2 = (const float*)d_in[11];
    const float* b2  = (const float*)d_in[12];
    const float* Ws3 = (const float*)d_in[13];
    const float* Wn3 = (const float*)d_in[14];
    const float* b3  = (const float*)d_in[15];
    float* out = (float*)d_out;

    float *bufA, *bufB, *z, *agg, *cnt;
    int *degi;
    cudaGetSymbolAddress((void**)&bufA, g_bufA);
    cudaGetSymbolAddress((void**)&bufB, g_bufB);
    cudaGetSymbolAddress((void**)&z, g_z);
    cudaGetSymbolAddress((void**)&agg, g_agg);
    cudaGetSymbolAddress((void**)&cnt, g_cnt);
    cudaGetSymbolAddress((void**)&degi, g_degi);

    const int T = 256;

    // ---- CSR build ----
    cudaMemsetAsync(degi, 0, NN * sizeof(int));
    k_degree<<<blks(NE, T), T>>>(dst);
    k_scan1<<<NB, 1024>>>();
    k_scan2<<<1, 256>>>();
    k_scan3<<<NB, 1024>>>();
    k_build<<<blks(NE, T), T>>>(src, dst);

    // ---- layer 0: 32 -> 128, relu ----
    k_gather4<32, 4><<<blks((long long)NN * 32, T), T>>>(feat, agg);
    {
        long long th = (long long)((NN + 3) / 4) * 32;
        k_sage0<4><<<blks(th, T), T>>>(feat, agg, Ws0, Wn0, b0, bufA);
    }

    // ---- layer 1: 128 -> 48, relu ----
    {
        long long th = (long long)((NN + 7) / 8) * 12;
        k_proj<128, 48, 8, false, false><<<blks(th, T), T>>>(bufA, Wn1, nullptr, nullptr, z);
    }
    k_gather4<48, 2><<<blks((long long)NN * 32, T), T>>>(z, agg);
    {
        long long th = (long long)((NN + 7) / 8) * 12;
        k_proj<128, 48, 8, true, true><<<blks(th, T), T>>>(bufA, Ws1, agg, b1, bufB);
    }

    // ---- layer 2: 48 -> 28, relu ----
    {
        long long th = (long long)((NN + 7) / 8) * 7;
        k_proj<48, 28, 8, false, false><<<blks(th, T), T>>>(bufB, Wn2, nullptr, nullptr, z);
    }
    k_gather4<28, 4><<<blks((long long)NN * 32, T), T>>>(z, agg);
    {
        long long th = (long long)((NN + 7) / 8) * 7;
        k_proj<48, 28, 8, true, true><<<blks(th, T), T>>>(bufB, Ws2, agg, b2, bufA);
    }

    // ---- layer 3: 28 -> 5, linear ----
    k_gemmS<28, 5><<<blks((long long)NN * 5, T), T>>>(bufA, Wn3, z);
    k_gatherS<5><<<blks((long long)NN * 32, T), T>>>(z, agg);
    k_postS<28, 5, false><<<blks((long long)NN * 5, T), T>>>(bufA, agg, Ws3, b3, bufB);

    // ---- readout ----
    cudaMemsetAsync(out, 0, NG * 5 * sizeof(float));
    cudaMemsetAsync(cnt, 0, NG * sizeof(float));
    k_readout<<<blks(NN, T), T>>>(bufB, gid, out);
    k_final<<<blks(NG * 5, T), T>>>(out);
}

// round 6
// speedup vs baseline: 1.5801x; 1.2648x over previous
#include <cuda_runtime.h>
#include <cuda_bf16.h>

static const int NN = 200000;
static const int NE = 3200000;
static const int NG = 400;
static const int NB = (NN + 1023) / 1024;  // 196 scan blocks

// Scratch (device globals; no runtime allocation allowed)
__device__ int   g_degi[NN];
__device__ int   g_off[NN + 1];
__device__ int   g_cursor[NN];
__device__ int   g_csr[NE];
__device__ int   g_bsum[256];
__device__ float g_bufA[(size_t)NN * 128];  // layer outputs (max 128)
__device__ float g_bufB[(size_t)NN * 48];
__device__ float g_z[(size_t)NN * 48];      // projected neighbor features
__device__ float g_s[(size_t)NN * 48];      // self-projection + bias
__device__ float g_agg[(size_t)NN * 32];    // layer-0 raw-feature aggregate
__device__ float g_cnt[NG];

// ---------------------------------------------------------------------------
__global__ void k_degree(const int* __restrict__ dst) {
    int e = blockIdx.x * blockDim.x + threadIdx.x;
    if (e < NE) atomicAdd(&g_degi[dst[e]], 1);
}

// ---- parallel exclusive scan of g_degi -> g_off ----
__global__ void k_scan1() {
    __shared__ int sh[1024];
    int t = threadIdx.x;
    int j = blockIdx.x * 1024 + t;
    sh[t] = (j < NN) ? g_degi[j] : 0;
    __syncthreads();
    for (int d = 512; d > 0; d >>= 1) {
        if (t < d) sh[t] += sh[t + d];
        __syncthreads();
    }
    if (t == 0) g_bsum[blockIdx.x] = sh[0];
}

__global__ void k_scan2() {
    __shared__ int sh[256];
    int t = threadIdx.x;
    int v = (t < NB) ? g_bsum[t] : 0;
    sh[t] = v;
    __syncthreads();
    for (int d = 1; d < 256; d <<= 1) {
        int x = (t >= d) ? sh[t - d] : 0;
        __syncthreads();
        sh[t] += x;
        __syncthreads();
    }
    g_bsum[t] = sh[t] - v;  // exclusive
}

__global__ void k_scan3() {
    __shared__ int sh[1024];
    int t = threadIdx.x;
    int j = blockIdx.x * 1024 + t;
    int v = (j < NN) ? g_degi[j] : 0;
    sh[t] = v;
    __syncthreads();
    for (int d = 1; d < 1024; d <<= 1) {
        int x = (t >= d) ? sh[t - d] : 0;
        __syncthreads();
        sh[t] += x;
        __syncthreads();
    }
    int excl = sh[t] - v + g_bsum[blockIdx.x];
    if (j < NN) {
        g_off[j] = excl;
        g_cursor[j] = excl;
    }
    if (j == NN - 1) g_off[NN] = excl + v;
}

__global__ void k_build(const int* __restrict__ src, const int* __restrict__ dst) {
    int e = blockIdx.x * blockDim.x + threadIdx.x;
    if (e >= NE) return;
    int p = atomicAdd(&g_cursor[dst[e]], 1);
    g_csr[p] = src[e];
}

// ---------------------------------------------------------------------------
// plain gather (layer 0): agg[v] = sum feat[nbr] / max(deg,1)
template <int DIM, int SLOTS>
__global__ void k_gather4(const float* __restrict__ z, float* __restrict__ agg) {
    constexpr int F4L = 32 / SLOTS;
    constexpr int NF4 = DIM / 4;
    int gt = blockIdx.x * blockDim.x + threadIdx.x;
    int v = gt >> 5;
    if (v >= NN) return;
    int lane = gt & 31;
    int slot = lane / F4L;
    int f4 = lane % F4L;
    bool act = (f4 < NF4);

    int beg = g_off[v];
    int end = g_off[v + 1];
    float4 acc = make_float4(0.f, 0.f, 0.f, 0.f);

    int e = beg;
    for (; e + 4 * SLOTS <= end; e += 4 * SLOTS) {
        int s0 = g_csr[e + slot];
        int s1 = g_csr[e + SLOTS + slot];
        int s2 = g_csr[e + 2 * SLOTS + slot];
        int s3 = g_csr[e + 3 * SLOTS + slot];
        if (act) {
            float4 t0 = __ldg(reinterpret_cast<const float4*>(z + (size_t)s0 * DIM) + f4);
            float4 t1 = __ldg(reinterpret_cast<const float4*>(z + (size_t)s1 * DIM) + f4);
            float4 t2 = __ldg(reinterpret_cast<const float4*>(z + (size_t)s2 * DIM) + f4);
            float4 t3 = __ldg(reinterpret_cast<const float4*>(z + (size_t)s3 * DIM) + f4);
            acc.x += (t0.x + t1.x) + (t2.x + t3.x);
            acc.y += (t0.y + t1.y) + (t2.y + t3.y);
            acc.z += (t0.z + t1.z) + (t2.z + t3.z);
            acc.w += (t0.w + t1.w) + (t2.w + t3.w);
        }
    }
    for (; e < end; e += SLOTS) {
        int myE = e + slot;
        if (myE < end && act) {
            int s0 = g_csr[myE];
            float4 t0 = __ldg(reinterpret_cast<const float4*>(z + (size_t)s0 * DIM) + f4);
            acc.x += t0.x; acc.y += t0.y; acc.z += t0.z; acc.w += t0.w;
        }
    }
#pragma unroll
    for (int m = F4L; m < 32; m <<= 1) {
        acc.x += __shfl_xor_sync(0xFFFFFFFFu, acc.x, m);
        acc.y += __shfl_xor_sync(0xFFFFFFFFu, acc.y, m);
        acc.z += __shfl_xor_sync(0xFFFFFFFFu, acc.z, m);
        acc.w += __shfl_xor_sync(0xFFFFFFFFu, acc.w, m);
    }
    float inv = 1.0f / fmaxf((float)(end - beg), 1.0f);
    if (slot == 0 && act) {
        float4 o = make_float4(acc.x * inv, acc.y * inv, acc.z * inv, acc.w * inv);
        reinterpret_cast<float4*>(agg + (size_t)v * DIM)[f4] = o;
    }
}

// fused gather (layers 1,2): out[v] = act( s[v] + sum z[nbr]/max(deg,1) )
template <int DIM, int SLOTS, bool RELU>
__global__ void k_gatherF(const float* __restrict__ z, const float* __restrict__ s,
                          float* __restrict__ out) {
    constexpr int F4L = 32 / SLOTS;
    constexpr int NF4 = DIM / 4;
    int gt = blockIdx.x * blockDim.x + threadIdx.x;
    int v = gt >> 5;
    if (v >= NN) return;
    int lane = gt & 31;
    int slot = lane / F4L;
    int f4 = lane % F4L;
    bool act = (f4 < NF4);

    int beg = g_off[v];
    int end = g_off[v + 1];
    float4 acc = make_float4(0.f, 0.f, 0.f, 0.f);

    int e = beg;
    for (; e + 4 * SLOTS <= end; e += 4 * SLOTS) {
        int s0 = g_csr[e + slot];
        int s1 = g_csr[e + SLOTS + slot];
        int s2 = g_csr[e + 2 * SLOTS + slot];
        int s3 = g_csr[e + 3 * SLOTS + slot];
        if (act) {
            float4 t0 = __ldg(reinterpret_cast<const float4*>(z + (size_t)s0 * DIM) + f4);
            float4 t1 = __ldg(reinterpret_cast<const float4*>(z + (size_t)s1 * DIM) + f4);
            float4 t2 = __ldg(reinterpret_cast<const float4*>(z + (size_t)s2 * DIM) + f4);
            float4 t3 = __ldg(reinterpret_cast<const float4*>(z + (size_t)s3 * DIM) + f4);
            acc.x += (t0.x + t1.x) + (t2.x + t3.x);
            acc.y += (t0.y + t1.y) + (t2.y + t3.y);
            acc.z += (t0.z + t1.z) + (t2.z + t3.z);
            acc.w += (t0.w + t1.w) + (t2.w + t3.w);
        }
    }
    for (; e < end; e += SLOTS) {
        int myE = e + slot;
        if (myE < end && act) {
            int s0 = g_csr[myE];
            float4 t0 = __ldg(reinterpret_cast<const float4*>(z + (size_t)s0 * DIM) + f4);
            acc.x += t0.x; acc.y += t0.y; acc.z += t0.z; acc.w += t0.w;
        }
    }
#pragma unroll
    for (int m = F4L; m < 32; m <<= 1) {
        acc.x += __shfl_xor_sync(0xFFFFFFFFu, acc.x, m);
        acc.y += __shfl_xor_sync(0xFFFFFFFFu, acc.y, m);
        acc.z += __shfl_xor_sync(0xFFFFFFFFu, acc.z, m);
        acc.w += __shfl_xor_sync(0xFFFFFFFFu, acc.w, m);
    }
    float inv = 1.0f / fmaxf((float)(end - beg), 1.0f);
    if (slot == 0 && act) {
        float4 sv = __ldg(reinterpret_cast<const float4*>(s + (size_t)v * DIM) + f4);
        float4 o = make_float4(sv.x + acc.x * inv, sv.y + acc.y * inv,
                               sv.z + acc.z * inv, sv.w + acc.w * inv);
        if (RELU) {
            o.x = fmaxf(o.x, 0.f); o.y = fmaxf(o.y, 0.f);
            o.z = fmaxf(o.z, 0.f); o.w = fmaxf(o.w, 0.f);
        }
        reinterpret_cast<float4*>(out + (size_t)v * DIM)[f4] = o;
    }
}

// fused scalar gather for DIM=5 (layer 3, no relu): 4 edge slots x 8 lanes
__global__ void k_gatherF5(const float* __restrict__ z, const float* __restrict__ s,
                           float* __restrict__ out) {
    constexpr int DIM = 5;
    int gt = blockIdx.x * blockDim.x + threadIdx.x;
    int v = gt >> 5;
    if (v >= NN) return;
    int lane = gt & 31;
    int slot = lane >> 3;      // 4 slots
    int f = lane & 7;          // 8 lanes/slot
    bool act = (f < DIM);

    int beg = g_off[v];
    int end = g_off[v + 1];
    float acc = 0.0f;
    int e = beg;
    for (; e + 8 <= end; e += 8) {
        int s0 = g_csr[e + slot];
        int s1 = g_csr[e + 4 + slot];
        if (act) acc += z[(size_t)s0 * DIM + f] + z[(size_t)s1 * DIM + f];
    }
    for (; e < end; e += 4) {
        int myE = e + slot;
        if (myE < end && act) acc += z[(size_t)g_csr[myE] * DIM + f];
    }
#pragma unroll
    for (int m = 8; m < 32; m <<= 1) acc += __shfl_xor_sync(0xFFFFFFFFu, acc, m);
    float inv = 1.0f / fmaxf((float)(end - beg), 1.0f);
    if (slot == 0 && act)
        out[(size_t)v * DIM + f] = s[(size_t)v * DIM + f] + acc * inv;
}

// ---------------------------------------------------------------------------
// Combined z/s projection: z = h@Wn ; s = h@Ws + b. Thread -> float4 x NV nodes.
template <int DIN, int DOUT, int NV>
__global__ void k_zs(const float* __restrict__ h, const float* __restrict__ Wn,
                     const float* __restrict__ Ws, const float* __restrict__ bias,
                     float* __restrict__ z, float* __restrict__ s) {
    constexpr int OG = DOUT / 4;
    long long t = (long long)blockIdx.x * blockDim.x + threadIdx.x;
    int oq = (int)(t % OG);
    long long ng = t / OG;
    int n0 = (int)(ng * NV);
    if (n0 >= NN) return;

    float4 b4 = __ldg(reinterpret_cast<const float4*>(bias) + oq);
    float4 az[NV], as[NV];
#pragma unroll
    for (int i = 0; i < NV; i++) {
        az[i] = make_float4(0.f, 0.f, 0.f, 0.f);
        as[i] = b4;
    }

#pragma unroll
    for (int k = 0; k < DIN; k += 4) {
        float4 n0w = __ldg(reinterpret_cast<const float4*>(Wn + (size_t)(k + 0) * DOUT) + oq);
        float4 n1w = __ldg(reinterpret_cast<const float4*>(Wn + (size_t)(k + 1) * DOUT) + oq);
        float4 n2w = __ldg(reinterpret_cast<const float4*>(Wn + (size_t)(k + 2) * DOUT) + oq);
        float4 n3w = __ldg(reinterpret_cast<const float4*>(Wn + (size_t)(k + 3) * DOUT) + oq);
        float4 s0w = __ldg(reinterpret_cast<const float4*>(Ws + (size_t)(k + 0) * DOUT) + oq);
        float4 s1w = __ldg(reinterpret_cast<const float4*>(Ws + (size_t)(k + 1) * DOUT) + oq);
        float4 s2w = __ldg(reinterpret_cast<const float4*>(Ws + (size_t)(k + 2) * DOUT) + oq);
        float4 s3w = __ldg(reinterpret_cast<const float4*>(Ws + (size_t)(k + 3) * DOUT) + oq);
#pragma unroll
        for (int i = 0; i < NV; i++) {
            int node = min(n0 + i, NN - 1);
            float4 hv = __ldg(reinterpret_cast<const float4*>(h + (size_t)node * DIN) + (k >> 2));
            az[i].x = fmaf(hv.x, n0w.x, fmaf(hv.y, n1w.x, fmaf(hv.z, n2w.x, fmaf(hv.w, n3w.x, az[i].x))));
            az[i].y = fmaf(hv.x, n0w.y, fmaf(hv.y, n1w.y, fmaf(hv.z, n2w.y, fmaf(hv.w, n3w.y, az[i].y))));
            az[i].z = fmaf(hv.x, n0w.z, fmaf(hv.y, n1w.z, fmaf(hv.z, n2w.z, fmaf(hv.w, n3w.z, az[i].z))));
            az[i].w = fmaf(hv.x, n0w.w, fmaf(hv.y, n1w.w, fmaf(hv.z, n2w.w, fmaf(hv.w, n3w.w, az[i].w))));
            as[i].x = fmaf(hv.x, s0w.x, fmaf(hv.y, s1w.x, fmaf(hv.z, s2w.x, fmaf(hv.w, s3w.x, as[i].x))));
            as[i].y = fmaf(hv.x, s0w.y, fmaf(hv.y, s1w.y, fmaf(hv.z, s2w.y, fmaf(hv.w, s3w.y, as[i].y))));
            as[i].z = fmaf(hv.x, s0w.z, fmaf(hv.y, s1w.z, fmaf(hv.z, s2w.z, fmaf(hv.w, s3w.z, as[i].z))));
            as[i].w = fmaf(hv.x, s0w.w, fmaf(hv.y, s1w.w, fmaf(hv.z, s2w.w, fmaf(hv.w, s3w.w, as[i].w))));
        }
    }

#pragma unroll
    for (int i = 0; i < NV; i++) {
        if (n0 + i < NN) {
            reinterpret_cast<float4*>(z + (size_t)(n0 + i) * DOUT)[oq] = az[i];
            reinterpret_cast<float4*>(s + (size_t)(n0 + i) * DOUT)[oq] = as[i];
        }
    }
}

// scalar combined z/s for DOUT=5 (layer 3)
template <int DIN, int DOUT>
__global__ void k_zsS(const float* __restrict__ h, const float* __restrict__ Wn,
                      const float* __restrict__ Ws, const float* __restrict__ bias,
                      float* __restrict__ z, float* __restrict__ s) {
    long long idx = (long long)blockIdx.x * blockDim.x + threadIdx.x;
    if (idx >= (long long)NN * DOUT) return;
    int v = (int)(idx / DOUT);
    int o = (int)(idx % DOUT);
    const float* hrow = h + (size_t)v * DIN;
    float accz = 0.0f;
    float accs = bias[o];
#pragma unroll
    for (int k = 0; k < DIN; k++) {
        float hv = hrow[k];
        accz = fmaf(hv, Wn[k * DOUT + o], accz);
        accs = fmaf(hv, Ws[k * DOUT + o], accs);
    }
    z[idx] = accz;
    s[idx] = accs;
}

// Fused layer-0: out = relu( feat@Ws + agg@Wn + b ), DIN=32, DOUT=128
template <int NV>
__global__ void k_sage0(const float* __restrict__ feat, const float* __restrict__ agg,
                        const float* __restrict__ Ws, const float* __restrict__ Wn,
                        const float* __restrict__ bias, float* __restrict__ out) {
    constexpr int DIN = 32, DOUT = 128, OG = 32;
    long long t = (long long)blockIdx.x * blockDim.x + threadIdx.x;
    int oq = (int)(t % OG);
    long long ng = t / OG;
    int n0 = (int)(ng * NV);
    if (n0 >= NN) return;

    float4 b4 = __ldg(reinterpret_cast<const float4*>(bias) + oq);
    float4 acc[NV];
#pragma unroll
    for (int i = 0; i < NV; i++) acc[i] = b4;

#pragma unroll
    for (int k = 0; k < DIN; k += 4) {
        float4 ws0 = __ldg(reinterpret_cast<const float4*>(Ws + (size_t)(k + 0) * DOUT) + oq);
        float4 ws1 = __ldg(reinterpret_cast<const float4*>(Ws + (size_t)(k + 1) * DOUT) + oq);
        float4 ws2 = __ldg(reinterpret_cast<const float4*>(Ws + (size_t)(k + 2) * DOUT) + oq);
        float4 ws3 = __ldg(reinterpret_cast<const float4*>(Ws + (size_t)(k + 3) * DOUT) + oq);
        float4 wn0 = __ldg(reinterpret_cast<const float4*>(Wn + (size_t)(k + 0) * DOUT) + oq);
        float4 wn1 = __ldg(reinterpret_cast<const float4*>(Wn + (size_t)(k + 1) * DOUT) + oq);
        float4 wn2 = __ldg(reinterpret_cast<const float4*>(Wn + (size_t)(k + 2) * DOUT) + oq);
        float4 wn3 = __ldg(reinterpret_cast<const float4*>(Wn + (size_t)(k + 3) * DOUT) + oq);
#pragma unroll
        for (int i = 0; i < NV; i++) {
            int node = min(n0 + i, NN - 1);
            float4 hv = __ldg(reinterpret_cast<const float4*>(feat + (size_t)node * DIN) + (k >> 2));
            float4 av = __ldg(reinterpret_cast<const float4*>(agg + (size_t)node * DIN) + (k >> 2));
            acc[i].x = fmaf(hv.x, ws0.x, fmaf(hv.y, ws1.x, fmaf(hv.z, ws2.x, fmaf(hv.w, ws3.x, acc[i].x))));
            acc[i].y = fmaf(hv.x, ws0.y, fmaf(hv.y, ws1.y, fmaf(hv.z, ws2.y, fmaf(hv.w, ws3.y, acc[i].y))));
            acc[i].z = fmaf(hv.x, ws0.z, fmaf(hv.y, ws1.z, fmaf(hv.z, ws2.z, fmaf(hv.w, ws3.z, acc[i].z))));
            acc[i].w = fmaf(hv.x, ws0.w, fmaf(hv.y, ws1.w, fmaf(hv.z, ws2.w, fmaf(hv.w, ws3.w, acc[i].w))));
            acc[i].x = fmaf(av.x, wn0.x, fmaf(av.y, wn1.x, fmaf(av.z, wn2.x, fmaf(av.w, wn3.x, acc[i].x))));
            acc[i].y = fmaf(av.x, wn0.y, fmaf(av.y, wn1.y, fmaf(av.z, wn2.y, fmaf(av.w, wn3.y, acc[i].y))));
            acc[i].z = fmaf(av.x, wn0.z, fmaf(av.y, wn1.z, fmaf(av.z, wn2.z, fmaf(av.w, wn3.z, acc[i].z))));
            acc[i].w = fmaf(av.x, wn0.w, fmaf(av.y, wn1.w, fmaf(av.z, wn2.w, fmaf(av.w, wn3.w, acc[i].w))));
        }
    }

#pragma unroll
    for (int i = 0; i < NV; i++) {
        if (n0 + i < NN) {
            float4 r = acc[i];
            r.x = fmaxf(r.x, 0.f); r.y = fmaxf(r.y, 0.f);
            r.z = fmaxf(r.z, 0.f); r.w = fmaxf(r.w, 0.f);
            reinterpret_cast<float4*>(out + (size_t)(n0 + i) * DOUT)[oq] = r;
        }
    }
}

// ---------------------------------------------------------------------------
// warp-aggregated readout (gid sorted -> warps mostly single-graph)
__global__ void k_readout(const float* __restrict__ h, const int* __restrict__ gid,
                          float* __restrict__ out) {
    int v = blockIdx.x * blockDim.x + threadIdx.x;
    bool ok = (v < NN);
    int g = ok ? gid[v] : -1;
    float c = ok ? 1.0f : 0.0f;
    float f0 = 0, f1 = 0, f2 = 0, f3 = 0, f4 = 0;
    if (ok) {
        const float* hr = h + (size_t)v * 5;
        f0 = hr[0]; f1 = hr[1]; f2 = hr[2]; f3 = hr[3]; f4 = hr[4];
    }
    int g0 = __shfl_sync(0xFFFFFFFFu, ok ? g : __shfl_sync(0xFFFFFFFFu, g, 0), 0);
    bool uniform = __all_sync(0xFFFFFFFFu, !ok || g == g0);
    if (uniform) {
#pragma unroll
        for (int m = 16; m > 0; m >>= 1) {
            c  += __shfl_xor_sync(0xFFFFFFFFu, c, m);
            f0 += __shfl_xor_sync(0xFFFFFFFFu, f0, m);
            f1 += __shfl_xor_sync(0xFFFFFFFFu, f1, m);
            f2 += __shfl_xor_sync(0xFFFFFFFFu, f2, m);
            f3 += __shfl_xor_sync(0xFFFFFFFFu, f3, m);
            f4 += __shfl_xor_sync(0xFFFFFFFFu, f4, m);
        }
        if ((threadIdx.x & 31) == 0 && c > 0.0f) {
            atomicAdd(&g_cnt[g0], c);
            atomicAdd(&out[g0 * 5 + 0], f0);
            atomicAdd(&out[g0 * 5 + 1], f1);
            atomicAdd(&out[g0 * 5 + 2], f2);
            atomicAdd(&out[g0 * 5 + 3], f3);
            atomicAdd(&out[g0 * 5 + 4], f4);
        }
    } else if (ok) {
        atomicAdd(&g_cnt[g], 1.0f);
        atomicAdd(&out[g * 5 + 0], f0);
        atomicAdd(&out[g * 5 + 1], f1);
        atomicAdd(&out[g * 5 + 2], f2);
        atomicAdd(&out[g * 5 + 3], f3);
        atomicAdd(&out[g * 5 + 4], f4);
    }
}

__global__ void k_final(float* __restrict__ out) {
    int i = blockIdx.x * blockDim.x + threadIdx.x;
    if (i < NG * 5) out[i] /= fmaxf(g_cnt[i / 5], 1.0f);
}

// ---------------------------------------------------------------------------
static inline int blks(long long n, int t) { return (int)((n + t - 1) / t); }

extern "C" void kernel_launch(void* const* d_in, const int* in_sizes, int n_in,
                              void* d_out, int out_size) {
    const float* feat = (const float*)d_in[0];
    const int* src = (const int*)d_in[1];
    const int* dst = (const int*)d_in[2];
    const int* gid = (const int*)d_in[3];
    const float* Ws0 = (const float*)d_in[4];
    const float* Wn0 = (const float*)d_in[5];
    const float* b0  = (const float*)d_in[6];
    const float* Ws1 = (const float*)d_in[7];
    const float* Wn1 = (const float*)d_in[8];
    const float* b1  = (const float*)d_in[9];
    const float* Ws2 = (const float*)d_in[10];
    const float* Wn2 = (const float*)d_in[11];
    const float* b2  = (const float*)d_in[12];
    const float* Ws3 = (const float*)d_in[13];
    const float* Wn3 = (const float*)d_in[14];
    const float* b3  = (const float*)d_in[15];
    float* out = (float*)d_out;

    float *bufA, *bufB, *z, *s, *agg, *cnt;
    int *degi;
    cudaGetSymbolAddress((void**)&bufA, g_bufA);
    cudaGetSymbolAddress((void**)&bufB, g_bufB);
    cudaGetSymbolAddress((void**)&z, g_z);
    cudaGetSymbolAddress((void**)&s, g_s);
    cudaGetSymbolAddress((void**)&agg, g_agg);
    cudaGetSymbolAddress((void**)&cnt, g_cnt);
    cudaGetSymbolAddress((void**)&degi, g_degi);

    const int T = 256;

    // ---- CSR build ----
    cudaMemsetAsync(degi, 0, NN * sizeof(int));
    k_degree<<<blks(NE, T), T>>>(dst);
    k_scan1<<<NB, 1024>>>();
    k_scan2<<<1, 256>>>();
    k_scan3<<<NB, 1024>>>();
    k_build<<<blks(NE, T), T>>>(src, dst);

    // ---- layer 0: 32 -> 128, relu ----
    k_gather4<32, 4><<<blks((long long)NN * 32, T), T>>>(feat, agg);
    {
        long long th = (long long)((NN + 3) / 4) * 32;
        k_sage0<4><<<blks(th, T), T>>>(feat, agg, Ws0, Wn0, b0, bufA);
    }

    // ---- layer 1: 128 -> 48, relu ----
    {
        long long th = (long long)((NN + 3) / 4) * 12;
        k_zs<128, 48, 4><<<blks(th, T), T>>>(bufA, Wn1, Ws1, b1, z, s);
    }
    k_gatherF<48, 2, true><<<blks((long long)NN * 32, T), T>>>(z, s, bufB);

    // ---- layer 2: 48 -> 28, relu ----
    {
        long long th = (long long)((NN + 3) / 4) * 7;
        k_zs<48, 28, 4><<<blks(th, T), T>>>(bufB, Wn2, Ws2, b2, z, s);
    }
    k_gatherF<28, 4, true><<<blks((long long)NN * 32, T), T>>>(z, s, bufA);

    // ---- layer 3: 28 -> 5, linear ----
    k_zsS<28, 5><<<blks((long long)NN * 5, T), T>>>(bufA, Wn3, Ws3, b3, z, s);
    k_gatherF5<<<blks((long long)NN * 32, T), T>>>(z, s, bufB);

    // ---- readout ----
    cudaMemsetAsync(out, 0, NG * 5 * sizeof(float));
    cudaMemsetAsync(cnt, 0, NG * sizeof(float));
    k_readout<<<blks(NN, T), T>>>(bufB, gid, out);
    k_final<<<blks(NG * 5, T), T>>>(out);
}